// round 15
// baseline (speedup 1.0000x reference)
#include <cuda_runtime.h>
#include <cuda_fp16.h>
#include <math.h>
#include <stdint.h>

// Problem constants
#define S_    2048
#define H_    2048
#define NH_   16
#define HD_   128
#define ROT_  32
#define FF_   8192
#define L_    2
#define V_    32000
#define EPS_  1e-5f

// ---------------------------------------------------------------------------
// Scratch (static device globals)
// ---------------------------------------------------------------------------
__device__ float g_h   [(size_t)S_ * H_];
__device__ float g_mlp [(size_t)S_ * H_];
__device__ float g_attn[(size_t)S_ * H_];

// fp16 activations
__device__ __half g_a1f[(size_t)S_ * H_];
__device__ __half g_a2f[(size_t)S_ * H_];
__device__ __half g_ff [(size_t)S_ * FF_];
__device__ __half g_qf [(size_t)S_ * 3 * H_];
__device__ __half g_vtf[(size_t)NH_ * HD_ * S_];
__device__ __half g_pf [(size_t)NH_ * S_ * S_];   // scores, then probs (in place)
__device__ __half g_ctxf[(size_t)S_ * H_];
__device__ __half g_af [(size_t)S_ * H_];

// per-GEMM transposed fp16 weights
__device__ __half g_wq [(size_t)L_ * H_ * 3 * H_];
__device__ __half g_wd [(size_t)L_ * H_ * H_];
__device__ __half g_wf1[(size_t)L_ * H_ * FF_];
__device__ __half g_wf2[(size_t)L_ * FF_ * H_];
__device__ __half g_wlf[(size_t)V_ * H_];

// ---------------------------------------------------------------------------
// Helpers
// ---------------------------------------------------------------------------
__device__ __forceinline__ uint32_t smem_u32(const void* p) {
    uint32_t a;
    asm("{ .reg .u64 t; cvta.to.shared.u64 t, %1; cvt.u32.u64 %0, t; }"
        : "=r"(a) : "l"(p));
    return a;
}
__device__ __forceinline__ uint32_t swz(uint32_t off) {
    return off ^ ((off >> 3) & 0x70);
}
__device__ __forceinline__ float gelu_f(float x) {
    float t = tanhf(0.79788456f * x * (1.f + 0.044715f * x * x));
    return 0.5f * x * (1.f + t);
}
__device__ __forceinline__ void ldsm4(uint32_t (&r)[4], uint32_t addr) {
    asm volatile("ldmatrix.sync.aligned.m8n8.x4.shared.b16 {%0,%1,%2,%3}, [%4];"
                 : "=r"(r[0]), "=r"(r[1]), "=r"(r[2]), "=r"(r[3]) : "r"(addr));
}
__device__ __forceinline__ void mma16816h(float (&d)[4], const uint32_t (&a)[4],
                                          const uint32_t* b) {
    asm volatile(
        "mma.sync.aligned.m16n8k16.row.col.f32.f16.f16.f32 "
        "{%0,%1,%2,%3}, {%4,%5,%6,%7}, {%8,%9}, {%0,%1,%2,%3};"
        : "+f"(d[0]), "+f"(d[1]), "+f"(d[2]), "+f"(d[3])
        : "r"(a[0]), "r"(a[1]), "r"(a[2]), "r"(a[3]), "r"(b[0]), "r"(b[1]));
}
__device__ __forceinline__ void cpa16(uint32_t s, const void* g) {
    asm volatile("cp.async.cg.shared.global [%0], [%1], 16;" :: "r"(s), "l"(g));
}

// ---------------------------------------------------------------------------
// Transpose fp32 -> fp16: W[Kd rows][N cols] (ldw) -> WT[N][Kd], z-batched
// ---------------------------------------------------------------------------
__global__ void wsplitf_kernel(const float* __restrict__ W, int ldw, int Kd, int N,
                               long long zin, long long zout,
                               __half* __restrict__ WT) {
    W  += (size_t)blockIdx.z * zin;
    WT += (size_t)blockIdx.z * zout;

    __shared__ float s[32][33];
    const int k0 = blockIdx.x * 32;
    const int n0 = blockIdx.y * 32;
    const int tid = threadIdx.x;
    const int r  = tid >> 3;
    const int c4 = (tid & 7) * 4;

    float4 v = *(const float4*)(W + (size_t)(k0 + r) * ldw + n0 + c4);
    s[r][c4 + 0] = v.x; s[r][c4 + 1] = v.y;
    s[r][c4 + 2] = v.z; s[r][c4 + 3] = v.w;
    __syncthreads();

    __half2 p0 = __floats2half2_rn(s[c4 + 0][r], s[c4 + 1][r]);
    __half2 p1 = __floats2half2_rn(s[c4 + 2][r], s[c4 + 3][r]);
    size_t o = (size_t)(n0 + r) * Kd + k0 + c4;
    *(__half2*)(WT + o)     = p0;
    *(__half2*)(WT + o + 2) = p1;
}

// Transpose fp16 -> fp16 (v heads): V[Kd rows][...] (ldv) -> VT[N][Kd], z-batched
__global__ void vtranf_kernel(const __half* __restrict__ V, int ldv, int Kd, int N,
                              long long zin, long long zout,
                              __half* __restrict__ VT) {
    V  += (size_t)blockIdx.z * zin;
    VT += (size_t)blockIdx.z * zout;

    __shared__ __half s[32][40];
    const int k0 = blockIdx.x * 32;
    const int n0 = blockIdx.y * 32;
    const int tid = threadIdx.x;
    const int r  = tid >> 3;
    const int c4 = (tid & 7) * 4;

    uint2 v = *(const uint2*)(V + (size_t)(k0 + r) * ldv + n0 + c4);
    *(uint32_t*)&s[r][c4]     = v.x;
    *(uint32_t*)&s[r][c4 + 2] = v.y;
    __syncthreads();

    __half o0 = s[c4 + 0][r], o1 = s[c4 + 1][r];
    __half o2 = s[c4 + 2][r], o3 = s[c4 + 3][r];
    size_t o = (size_t)(n0 + r) * Kd + k0 + c4;
    VT[o + 0] = o0; VT[o + 1] = o1; VT[o + 2] = o2; VT[o + 3] = o3;
}

// ---------------------------------------------------------------------------
// Fused residual-add + dual LayerNorm.
// ---------------------------------------------------------------------------
__global__ void addln_kernel(float* __restrict__ h,
                             const float* __restrict__ attn,
                             const float* __restrict__ mlp,
                             const float* __restrict__ g1,
                             const float* __restrict__ b1,
                             __half* __restrict__ o1,
                             const float* __restrict__ g2,
                             const float* __restrict__ b2,
                             __half* __restrict__ o2) {
    const int s = blockIdx.x;
    const int tid = threadIdx.x;
    float* row = h + (size_t)s * H_;
    const size_t base = (size_t)s * H_;
    __shared__ float red[256];

    float v[8];
    float lsum = 0.f;
#pragma unroll
    for (int i = 0; i < 8; i++) {
        int c = tid + i * 256;
        float val = row[c];
        if (attn) val += attn[base + c];
        if (mlp)  val += mlp[base + c];
        v[i] = val;
        lsum += val;
    }
    if (attn) {
#pragma unroll
        for (int i = 0; i < 8; i++) row[tid + i * 256] = v[i];
    }
    red[tid] = lsum; __syncthreads();
    for (int o = 128; o > 0; o >>= 1) {
        if (tid < o) red[tid] += red[tid + o];
        __syncthreads();
    }
    const float mean = red[0] * (1.f / H_);
    __syncthreads();

    float lvar = 0.f;
#pragma unroll
    for (int i = 0; i < 8; i++) { float d = v[i] - mean; lvar += d * d; }
    red[tid] = lvar; __syncthreads();
    for (int o = 128; o > 0; o >>= 1) {
        if (tid < o) red[tid] += red[tid + o];
        __syncthreads();
    }
    const float rstd = rsqrtf(red[0] * (1.f / H_) + EPS_);

#pragma unroll
    for (int i = 0; i < 8; i++) {
        int c = tid + i * 256;
        float nv = (v[i] - mean) * rstd;
        o1[base + c] = __float2half_rn(nv * g1[c] + b1[c]);
        if (o2) o2[base + c] = __float2half_rn(nv * g2[c] + b2[c]);
    }
}

// ---------------------------------------------------------------------------
// Register-resident causal softmax, in place on fp16 buffer.
// ---------------------------------------------------------------------------
__global__ void softmax_f16_kernel(__half* __restrict__ pf) {
    const int q = blockIdx.x;
    const int n = blockIdx.y;
    __half* row = pf + ((size_t)n * S_ + q) * (size_t)S_;
    const int len = q + 1;
    const int tid = threadIdx.x;
    __shared__ float red[256];

    float v[8];
#pragma unroll
    for (int i = 0; i < 8; i++) {
        int idx = tid + i * 256;
        v[i] = (idx < len) ? __half2float(row[idx]) : -3.4e38f;
    }
    float mx = v[0];
#pragma unroll
    for (int i = 1; i < 8; i++) mx = fmaxf(mx, v[i]);
    red[tid] = mx; __syncthreads();
    for (int o = 128; o > 0; o >>= 1) {
        if (tid < o) red[tid] = fmaxf(red[tid], red[tid + o]);
        __syncthreads();
    }
    mx = red[0]; __syncthreads();

    float sum = 0.f;
#pragma unroll
    for (int i = 0; i < 8; i++) {
        int idx = tid + i * 256;
        if (idx < len) { v[i] = expf(v[i] - mx); sum += v[i]; }
    }
    red[tid] = sum; __syncthreads();
    for (int o = 128; o > 0; o >>= 1) {
        if (tid < o) red[tid] += red[tid + o];
        __syncthreads();
    }
    const float inv = 1.f / red[0];

#pragma unroll
    for (int i = 0; i < 8; i++) {
        int idx = tid + i * 256;
        if (idx < len) row[idx] = __float2half_rn(v[i] * inv);
    }
    const int bend = ((q >> 7) + 1) << 7;
    const __half z = __float2half_rn(0.f);
    for (int idx = len + tid; idx < bend; idx += 256) row[idx] = z;
}

// ---------------------------------------------------------------------------
// Single-pass fp16 GEMM (R10-proven core): 2-stage cp.async pipeline, BK=64.
//   EPI: 0 = fp32 store, 1 = gelu -> fp16, 3 = fp16 store,
//        4 = fp16 store with fused bias + NeoX rotary (qkv GEMM).
//   CAUS: skip blocks with n0 > row0+127. CAUSK: K limited to row0+128
//         (block order reversed: longest blocks first).
// ---------------------------------------------------------------------------
template <int EPI, int BN, bool CAUS, bool CAUSK>
__global__ void __launch_bounds__(256, 1) gemm_hf(
    const __half* __restrict__ A, int lda, long long sA,
    const __half* __restrict__ B, int ldb, long long sB,
    const float* __restrict__ bias,
    float* __restrict__ C, __half* __restrict__ H16,
    int ldc, long long sC,
    int K, float alpha) {

    constexpr int MI  = (BN == 256) ? 4 : 2;
    constexpr int BUF = 16384 + BN * 128;

    extern __shared__ char smem[];
    const uint32_t sb = smem_u32(smem);
    const int tid  = threadIdx.x;
    const int lane = tid & 31;
    const int wid  = tid >> 5;
    const int wm   = (BN == 256) ? (wid & 1) : (wid & 3);
    const int wn   = (BN == 256) ? (wid >> 1) : (wid >> 2);
    const int mblk = CAUSK ? (gridDim.x - 1 - blockIdx.x) : blockIdx.x;
    const int row0 = mblk * 128;
    const int n0   = blockIdx.y * BN;

    if (CAUS && n0 > row0 + 127) return;

    A += (size_t)blockIdx.z * sA;
    B += (size_t)blockIdx.z * sB;
    if (C)   C   += (size_t)blockIdx.z * sC;
    if (H16) H16 += (size_t)blockIdx.z * sC;

    float acc[MI][8][4];
#pragma unroll
    for (int i = 0; i < MI; i++)
#pragma unroll
        for (int j = 0; j < 8; j++)
#pragma unroll
            for (int e = 0; e < 4; e++) acc[i][j][e] = 0.f;

    const int nch = CAUSK ? ((row0 + 128) >> 6) : (K >> 6);

    for (int c = 0; c <= nch; c++) {
        if (c < nch) {
            const uint32_t bufo = (uint32_t)(c & 1) * BUF;
            const int k0 = c << 6;
#pragma unroll
            for (int i = 0; i < 4; i++) {
                int idx = tid + i * 256;
                int r  = idx >> 3;
                int cc = (idx & 7) * 8;
                uint32_t soff = swz((uint32_t)(r * 128 + cc * 2));
                cpa16(sb + bufo + soff, A + (size_t)(row0 + r) * lda + k0 + cc);
            }
#pragma unroll
            for (int i = 0; i < BN / 32; i++) {
                int idx = tid + i * 256;
                int r  = idx >> 3;
                int cc = (idx & 7) * 8;
                uint32_t soff = swz((uint32_t)(r * 128 + cc * 2));
                cpa16(sb + bufo + 16384 + soff, B + (size_t)(n0 + r) * ldb + k0 + cc);
            }
            asm volatile("cp.async.commit_group;" ::: "memory");
        }
        if (c >= 1) {
            if (c < nch) asm volatile("cp.async.wait_group 1;" ::: "memory");
            else         asm volatile("cp.async.wait_group 0;" ::: "memory");
            __syncthreads();

            const uint32_t bufo = (uint32_t)((c - 1) & 1) * BUF;
            const uint32_t sA16 = sb + bufo;
            const uint32_t sB16 = sA16 + 16384;

#pragma unroll
            for (int ks = 0; ks < 4; ks++) {
                const int kk = ks * 16;
                uint32_t ah[MI][4];
                {
                    const uint32_t arow = (uint32_t)(wm * (MI * 16) + (lane & 15));
                    const uint32_t acol = (uint32_t)(kk + (lane >> 4) * 8);
#pragma unroll
                    for (int mi = 0; mi < MI; mi++) {
                        uint32_t off = swz((arow + mi * 16) * 128 + acol * 2);
                        ldsm4(ah[mi], sA16 + off);
                    }
                }
                const uint32_t brow = (uint32_t)(wn * 64 + ((lane >> 4) & 1) * 8 + (lane & 7));
                const uint32_t bcol = (uint32_t)(kk + ((lane >> 3) & 1) * 8);
#pragma unroll
                for (int ng = 0; ng < 4; ng++) {
                    uint32_t bh[4];
                    uint32_t off = swz((brow + ng * 16) * 128 + bcol * 2);
                    ldsm4(bh, sB16 + off);
#pragma unroll
                    for (int mi = 0; mi < MI; mi++) {
#pragma unroll
                        for (int half = 0; half < 2; half++) {
                            mma16816h(acc[mi][ng * 2 + half], ah[mi], bh + half * 2);
                        }
                    }
                }
            }
            __syncthreads();
        }
    }

    const int g = lane >> 2;
    const int t = lane & 3;

    if (EPI == 4) {
        // fold bias into acc (alpha == 1 for qkv)
#pragma unroll
        for (int mi = 0; mi < MI; mi++)
#pragma unroll
            for (int nt = 0; nt < 8; nt++) {
                const int col = n0 + wn * 64 + nt * 8 + 2 * t;
                float2 bv = *(const float2*)(bias + col);
                acc[mi][nt][0] += bv.x; acc[mi][nt][1] += bv.y;
                acc[mi][nt][2] += bv.x; acc[mi][nt][3] += bv.y;
            }
        // NeoX rotary: rot regions [0,32) (q) / [128,160) (k) per 384-col head,
        // both start at a 64-aligned warp span; pair (i, i+16) = (nt, nt+2).
        const int m384 = (n0 + wn * 64) % 384;
        if (m384 == 0 || m384 == 128) {
#pragma unroll
            for (int mi = 0; mi < MI; mi++)
#pragma unroll
                for (int nt = 0; nt < 2; nt++)
#pragma unroll
                    for (int e = 0; e < 4; e++) {
                        int i = nt * 8 + 2 * t + (e & 1);
                        int srow = row0 + wm * (MI * 16) + mi * 16 + g + ((e >> 1) * 8);
                        float f = expf(-(float)i * 0.575646273248511f);
                        float sn, cs;
                        sincosf((float)srow * f, &sn, &cs);
                        float a  = acc[mi][nt][e];
                        float c2 = acc[mi][nt + 2][e];
                        acc[mi][nt][e]     = a * cs - c2 * sn;
                        acc[mi][nt + 2][e] = c2 * cs + a * sn;
                    }
        }
    }

#pragma unroll
    for (int mi = 0; mi < MI; mi++) {
        const int r = row0 + wm * (MI * 16) + mi * 16 + g;
#pragma unroll
        for (int nt = 0; nt < 8; nt++) {
            const int col = n0 + wn * 64 + nt * 8 + 2 * t;
            float2 v0 = make_float2(acc[mi][nt][0] * alpha, acc[mi][nt][1] * alpha);
            float2 v1 = make_float2(acc[mi][nt][2] * alpha, acc[mi][nt][3] * alpha);
            if (EPI != 4 && bias) {
                float2 bv = *(const float2*)(bias + col);
                v0.x += bv.x; v0.y += bv.y;
                v1.x += bv.x; v1.y += bv.y;
            }
            if (EPI == 1 || EPI == 3 || EPI == 4) {
                if (EPI == 1) {
                    v0.x = gelu_f(v0.x); v0.y = gelu_f(v0.y);
                    v1.x = gelu_f(v1.x); v1.y = gelu_f(v1.y);
                }
                *(__half2*)(H16 + (size_t)r * ldc + col)       = __floats2half2_rn(v0.x, v0.y);
                *(__half2*)(H16 + (size_t)(r + 8) * ldc + col) = __floats2half2_rn(v1.x, v1.y);
            } else {
                float* p0 = C + (size_t)r * ldc + col;
                float* p1 = C + (size_t)(r + 8) * ldc + col;
                *(float2*)p0 = v0;
                *(float2*)p1 = v1;
            }
        }
    }
}

// ---------------------------------------------------------------------------
// Embedding gather
// ---------------------------------------------------------------------------
__global__ void embed_kernel(const int* __restrict__ x,
                             const float* __restrict__ embed,
                             float* __restrict__ h) {
    int s = blockIdx.y;
    int c = blockIdx.x * 256 + threadIdx.x;
    h[(size_t)s * H_ + c] = embed[(size_t)x[s] * H_ + c];
}

// ---------------------------------------------------------------------------
// Launcher with 3-stream fork/join (capture-safe: full join before return)
// ---------------------------------------------------------------------------
#define SM_H256 (2 * (16384 + 256 * 128))
#define SM_H128 (2 * (16384 + 128 * 128))

extern "C" void kernel_launch(void* const* d_in, const int* in_sizes, int n_in,
                              void* d_out, int out_size) {
    const int*   x        = (const int*)  d_in[0];
    const float* embed    = (const float*)d_in[1];
    const float* ln1_g    = (const float*)d_in[2];
    const float* ln1_b    = (const float*)d_in[3];
    const float* ln2_g    = (const float*)d_in[4];
    const float* ln2_b    = (const float*)d_in[5];
    const float* qkv_w    = (const float*)d_in[6];
    const float* qkv_b    = (const float*)d_in[7];
    const float* dense_w  = (const float*)d_in[8];
    const float* dense_b  = (const float*)d_in[9];
    const float* fc1_w    = (const float*)d_in[10];
    const float* fc1_b    = (const float*)d_in[11];
    const float* fc2_w    = (const float*)d_in[12];
    const float* fc2_b    = (const float*)d_in[13];
    const float* fln_g    = (const float*)d_in[14];
    const float* fln_b    = (const float*)d_in[15];
    const float* logits_w = (const float*)d_in[16];
    float* out = (float*)d_out;

    float *h, *mlp, *attn;
    __half *a1f, *a2f, *ff, *qf, *vtf, *pf, *ctxf, *af;
    __half *wq, *wd, *wf1, *wf2, *wlf;
    cudaGetSymbolAddress((void**)&h,      g_h);
    cudaGetSymbolAddress((void**)&mlp,    g_mlp);
    cudaGetSymbolAddress((void**)&attn,   g_attn);
    cudaGetSymbolAddress((void**)&a1f,    g_a1f);
    cudaGetSymbolAddress((void**)&a2f,    g_a2f);
    cudaGetSymbolAddress((void**)&ff,     g_ff);
    cudaGetSymbolAddress((void**)&qf,     g_qf);
    cudaGetSymbolAddress((void**)&vtf,    g_vtf);
    cudaGetSymbolAddress((void**)&pf,     g_pf);
    cudaGetSymbolAddress((void**)&ctxf,   g_ctxf);
    cudaGetSymbolAddress((void**)&af,     g_af);
    cudaGetSymbolAddress((void**)&wq,     g_wq);
    cudaGetSymbolAddress((void**)&wd,     g_wd);
    cudaGetSymbolAddress((void**)&wf1,    g_wf1);
    cudaGetSymbolAddress((void**)&wf2,    g_wf2);
    cudaGetSymbolAddress((void**)&wlf,    g_wlf);

    cudaFuncSetAttribute((const void*)gemm_hf<0, 256, false, false>,
                         cudaFuncAttributeMaxDynamicSharedMemorySize, SM_H256);
    cudaFuncSetAttribute((const void*)gemm_hf<1, 256, false, false>,
                         cudaFuncAttributeMaxDynamicSharedMemorySize, SM_H256);
    cudaFuncSetAttribute((const void*)gemm_hf<4, 256, false, false>,
                         cudaFuncAttributeMaxDynamicSharedMemorySize, SM_H256);
    cudaFuncSetAttribute((const void*)gemm_hf<3, 256, true, false>,
                         cudaFuncAttributeMaxDynamicSharedMemorySize, SM_H256);
    cudaFuncSetAttribute((const void*)gemm_hf<3, 128, false, true>,
                         cudaFuncAttributeMaxDynamicSharedMemorySize, SM_H128);

    // streams/events created once (first call is the non-captured correctness run)
    static cudaStream_t sW = 0, sM = 0;
    static cudaEvent_t evFork, evW[5], evLn[L_], evMlp[L_], evQkv[L_], evVt[L_];
    if (!sW) {
        cudaStreamCreateWithFlags(&sW, cudaStreamNonBlocking);
        cudaStreamCreateWithFlags(&sM, cudaStreamNonBlocking);
        cudaEventCreateWithFlags(&evFork, cudaEventDisableTiming);
        for (int i = 0; i < 5; i++) cudaEventCreateWithFlags(&evW[i], cudaEventDisableTiming);
        for (int i = 0; i < L_; i++) {
            cudaEventCreateWithFlags(&evLn[i], cudaEventDisableTiming);
            cudaEventCreateWithFlags(&evMlp[i], cudaEventDisableTiming);
            cudaEventCreateWithFlags(&evQkv[i], cudaEventDisableTiming);
            cudaEventCreateWithFlags(&evVt[i], cudaEventDisableTiming);
        }
    }

    const float inv_sqrt_hd = 0.08838834764831845f;  // 1/sqrt(128)

    // ---- fork ----
    cudaEventRecord(evFork, 0);
    cudaStreamWaitEvent(sW, evFork, 0);
    cudaStreamWaitEvent(sM, evFork, 0);

    // ---- weight prep on sW (fp16, z batches both layers) ----
    wsplitf_kernel<<<dim3(H_ / 32, 3 * H_ / 32, L_), 256, 0, sW>>>(
        qkv_w, 3 * H_, H_, 3 * H_, (long long)H_ * 3 * H_, (long long)H_ * 3 * H_, wq);
    cudaEventRecord(evW[0], sW);
    wsplitf_kernel<<<dim3(H_ / 32, FF_ / 32, L_), 256, 0, sW>>>(
        fc1_w, FF_, H_, FF_, (long long)H_ * FF_, (long long)H_ * FF_, wf1);
    cudaEventRecord(evW[1], sW);
    wsplitf_kernel<<<dim3(FF_ / 32, H_ / 32, L_), 256, 0, sW>>>(
        fc2_w, H_, FF_, H_, (long long)FF_ * H_, (long long)FF_ * H_, wf2);
    cudaEventRecord(evW[2], sW);
    wsplitf_kernel<<<dim3(H_ / 32, H_ / 32, L_), 256, 0, sW>>>(
        dense_w, H_, H_, H_, (long long)H_ * H_, (long long)H_ * H_, wd);
    cudaEventRecord(evW[3], sW);
    wsplitf_kernel<<<dim3(H_ / 32, V_ / 32, 1), 256, 0, sW>>>(
        logits_w, V_, H_, V_, 0, 0, wlf);
    cudaEventRecord(evW[4], sW);

    // ---- main path ----
    embed_kernel<<<dim3(H_ / 256, S_), 256>>>(x, embed, h);
    addln_kernel<<<S_, 256>>>(h, nullptr, nullptr,
                              ln1_g, ln1_b, a1f, ln2_g, ln2_b, a2f);
    cudaEventRecord(evLn[0], 0);

    for (int l = 0; l < L_; l++) {
        // ---- MLP branch on sM ----
        cudaStreamWaitEvent(sM, evLn[l], 0);
        cudaStreamWaitEvent(sM, evW[1], 0);
        gemm_hf<1, 256, false, false><<<dim3(S_ / 128, FF_ / 256, 1), 256, SM_H256, sM>>>(
            a2f, H_, 0, wf1 + (size_t)l * H_ * FF_, H_, 0,
            fc1_b + (size_t)l * FF_, nullptr, ff, FF_, 0, H_, 1.f);
        cudaStreamWaitEvent(sM, evW[2], 0);
        gemm_hf<0, 256, false, false><<<dim3(S_ / 128, H_ / 256, 1), 256, SM_H256, sM>>>(
            ff, FF_, 0, wf2 + (size_t)l * FF_ * H_, FF_, 0,
            fc2_b + (size_t)l * H_, mlp, nullptr, H_, 0, FF_, 1.f);
        cudaEventRecord(evMlp[l], sM);

        // ---- attention branch on main ----
        cudaStreamWaitEvent(0, evW[0], 0);
        // qkv GEMM with fused bias + rotary epilogue
        gemm_hf<4, 256, false, false><<<dim3(S_ / 128, 3 * H_ / 256, 1), 256, SM_H256>>>(
            a1f, H_, 0, wq + (size_t)l * H_ * 3 * H_, H_, 0,
            qkv_b + (size_t)l * 3 * H_, nullptr, qf, 3 * H_, 0, H_, 1.f);
        cudaEventRecord(evQkv[l], 0);

        // v transpose on sW (idle after weight prep) in parallel with scores
        cudaStreamWaitEvent(sW, evQkv[l], 0);
        vtranf_kernel<<<dim3(S_ / 32, HD_ / 32, NH_), 256, 0, sW>>>(
            qf + 2 * HD_, 3 * H_, S_, HD_, 3 * HD_, (long long)HD_ * S_, vtf);
        cudaEventRecord(evVt[l], sW);

        // scores = q @ k^T * 1/sqrt(HD)  (fp16 out, causal block-skip) -> pf
        gemm_hf<3, 256, true, false><<<dim3(S_ / 128, S_ / 256, NH_), 256, SM_H256>>>(
            qf, 3 * H_, 3 * HD_,
            qf + HD_, 3 * H_, 3 * HD_,
            nullptr, nullptr, pf, S_, (long long)S_ * S_,
            HD_, inv_sqrt_hd);

        softmax_f16_kernel<<<dim3(S_, NH_), 256>>>(pf);

        // ctx = probs @ v  (fp16, causal K-limit, longest blocks first) -> ctxf
        cudaStreamWaitEvent(0, evVt[l], 0);
        gemm_hf<3, 128, false, true><<<dim3(S_ / 128, 1, NH_), 256, SM_H128>>>(
            pf, S_, (long long)S_ * S_,
            vtf, S_, (long long)HD_ * S_,
            nullptr, nullptr, ctxf, H_, HD_,
            S_, 1.f);

        // attn = ctx @ dense_w + dense_b  (fp32 out)
        cudaStreamWaitEvent(0, evW[3], 0);
        gemm_hf<0, 256, false, false><<<dim3(S_ / 128, H_ / 256, 1), 256, SM_H256>>>(
            ctxf, H_, 0, wd + (size_t)l * H_ * H_, H_, 0,
            dense_b + (size_t)l * H_, attn, nullptr, H_, 0, H_, 1.f);

        // join MLP; fused h += attn + mlp, then LN(s)
        cudaStreamWaitEvent(0, evMlp[l], 0);
        if (l < L_ - 1) {
            addln_kernel<<<S_, 256>>>(h, attn, mlp,
                                      ln1_g + (size_t)(l + 1) * H_,
                                      ln1_b + (size_t)(l + 1) * H_, a1f,
                                      ln2_g + (size_t)(l + 1) * H_,
                                      ln2_b + (size_t)(l + 1) * H_, a2f);
            cudaEventRecord(evLn[l + 1], 0);
        } else {
            addln_kernel<<<S_, 256>>>(h, attn, mlp,
                                      fln_g, fln_b, af,
                                      nullptr, nullptr, nullptr);
        }
    }

    // logits GEMM (joins sW via evW[4])
    cudaStreamWaitEvent(0, evW[4], 0);
    gemm_hf<0, 256, false, false><<<dim3(S_ / 128, V_ / 256, 1), 256, SM_H256>>>(
        af, H_, 0, wlf, H_, 0, nullptr, out, nullptr, V_, 0, H_, 1.f);
}

// round 16
// speedup vs baseline: 1.1016x; 1.1016x over previous
#include <cuda_runtime.h>
#include <cuda_fp16.h>
#include <math.h>
#include <stdint.h>

// Problem constants
#define S_    2048
#define H_    2048
#define NH_   16
#define HD_   128
#define ROT_  32
#define FF_   8192
#define L_    2
#define V_    32000
#define EPS_  1e-5f

// ---------------------------------------------------------------------------
// Scratch (static device globals)
// ---------------------------------------------------------------------------
__device__ float g_h   [(size_t)S_ * H_];
__device__ float g_mlp [(size_t)S_ * H_];
__device__ float g_attn[(size_t)S_ * H_];

// fp16 activations
__device__ __half g_a1f[(size_t)S_ * H_];
__device__ __half g_a2f[(size_t)S_ * H_];
__device__ __half g_ff [(size_t)S_ * FF_];
__device__ __half g_qf [(size_t)S_ * 3 * H_];
__device__ __half g_vtf[(size_t)NH_ * HD_ * S_];
__device__ __half g_pf [(size_t)NH_ * S_ * S_];   // scores, then probs (in place)
__device__ __half g_ctxf[(size_t)S_ * H_];
__device__ __half g_af [(size_t)S_ * H_];

// per-GEMM transposed fp16 weights
__device__ __half g_wq [(size_t)L_ * H_ * 3 * H_];
__device__ __half g_wd [(size_t)L_ * H_ * H_];
__device__ __half g_wf1[(size_t)L_ * H_ * FF_];
__device__ __half g_wf2[(size_t)L_ * FF_ * H_];
__device__ __half g_wlf[(size_t)V_ * H_];

// ---------------------------------------------------------------------------
// Helpers
// ---------------------------------------------------------------------------
__device__ __forceinline__ uint32_t smem_u32(const void* p) {
    uint32_t a;
    asm("{ .reg .u64 t; cvta.to.shared.u64 t, %1; cvt.u32.u64 %0, t; }"
        : "=r"(a) : "l"(p));
    return a;
}
__device__ __forceinline__ uint32_t swz(uint32_t off) {
    return off ^ ((off >> 3) & 0x70);
}
__device__ __forceinline__ float gelu_f(float x) {
    float t = tanhf(0.79788456f * x * (1.f + 0.044715f * x * x));
    return 0.5f * x * (1.f + t);
}
__device__ __forceinline__ void ldsm4(uint32_t (&r)[4], uint32_t addr) {
    asm volatile("ldmatrix.sync.aligned.m8n8.x4.shared.b16 {%0,%1,%2,%3}, [%4];"
                 : "=r"(r[0]), "=r"(r[1]), "=r"(r[2]), "=r"(r[3]) : "r"(addr));
}
__device__ __forceinline__ void mma16816h(float (&d)[4], const uint32_t (&a)[4],
                                          const uint32_t* b) {
    asm volatile(
        "mma.sync.aligned.m16n8k16.row.col.f32.f16.f16.f32 "
        "{%0,%1,%2,%3}, {%4,%5,%6,%7}, {%8,%9}, {%0,%1,%2,%3};"
        : "+f"(d[0]), "+f"(d[1]), "+f"(d[2]), "+f"(d[3])
        : "r"(a[0]), "r"(a[1]), "r"(a[2]), "r"(a[3]), "r"(b[0]), "r"(b[1]));
}
__device__ __forceinline__ void cpa16(uint32_t s, const void* g) {
    asm volatile("cp.async.cg.shared.global [%0], [%1], 16;" :: "r"(s), "l"(g));
}

// ---------------------------------------------------------------------------
// Transpose fp32 -> fp16: W[Kd rows][N cols] (ldw) -> WT[N][Kd], z-batched
// ---------------------------------------------------------------------------
__global__ void wsplitf_kernel(const float* __restrict__ W, int ldw, int Kd, int N,
                               long long zin, long long zout,
                               __half* __restrict__ WT) {
    W  += (size_t)blockIdx.z * zin;
    WT += (size_t)blockIdx.z * zout;

    __shared__ float s[32][33];
    const int k0 = blockIdx.x * 32;
    const int n0 = blockIdx.y * 32;
    const int tid = threadIdx.x;
    const int r  = tid >> 3;
    const int c4 = (tid & 7) * 4;

    float4 v = *(const float4*)(W + (size_t)(k0 + r) * ldw + n0 + c4);
    s[r][c4 + 0] = v.x; s[r][c4 + 1] = v.y;
    s[r][c4 + 2] = v.z; s[r][c4 + 3] = v.w;
    __syncthreads();

    __half2 p0 = __floats2half2_rn(s[c4 + 0][r], s[c4 + 1][r]);
    __half2 p1 = __floats2half2_rn(s[c4 + 2][r], s[c4 + 3][r]);
    size_t o = (size_t)(n0 + r) * Kd + k0 + c4;
    *(__half2*)(WT + o)     = p0;
    *(__half2*)(WT + o + 2) = p1;
}

// Transpose fp16 -> fp16 (v heads): V[Kd rows][...] (ldv) -> VT[N][Kd], z-batched
__global__ void vtranf_kernel(const __half* __restrict__ V, int ldv, int Kd, int N,
                              long long zin, long long zout,
                              __half* __restrict__ VT) {
    V  += (size_t)blockIdx.z * zin;
    VT += (size_t)blockIdx.z * zout;

    __shared__ __half s[32][40];
    const int k0 = blockIdx.x * 32;
    const int n0 = blockIdx.y * 32;
    const int tid = threadIdx.x;
    const int r  = tid >> 3;
    const int c4 = (tid & 7) * 4;

    uint2 v = *(const uint2*)(V + (size_t)(k0 + r) * ldv + n0 + c4);
    *(uint32_t*)&s[r][c4]     = v.x;
    *(uint32_t*)&s[r][c4 + 2] = v.y;
    __syncthreads();

    __half o0 = s[c4 + 0][r], o1 = s[c4 + 1][r];
    __half o2 = s[c4 + 2][r], o3 = s[c4 + 3][r];
    size_t o = (size_t)(n0 + r) * Kd + k0 + c4;
    VT[o + 0] = o0; VT[o + 1] = o1; VT[o + 2] = o2; VT[o + 3] = o3;
}

// ---------------------------------------------------------------------------
// Fused residual-add + dual LayerNorm.
// ---------------------------------------------------------------------------
__global__ void addln_kernel(float* __restrict__ h,
                             const float* __restrict__ attn,
                             const float* __restrict__ mlp,
                             const float* __restrict__ g1,
                             const float* __restrict__ b1,
                             __half* __restrict__ o1,
                             const float* __restrict__ g2,
                             const float* __restrict__ b2,
                             __half* __restrict__ o2) {
    const int s = blockIdx.x;
    const int tid = threadIdx.x;
    float* row = h + (size_t)s * H_;
    const size_t base = (size_t)s * H_;
    __shared__ float red[256];

    float v[8];
    float lsum = 0.f;
#pragma unroll
    for (int i = 0; i < 8; i++) {
        int c = tid + i * 256;
        float val = row[c];
        if (attn) val += attn[base + c];
        if (mlp)  val += mlp[base + c];
        v[i] = val;
        lsum += val;
    }
    if (attn) {
#pragma unroll
        for (int i = 0; i < 8; i++) row[tid + i * 256] = v[i];
    }
    red[tid] = lsum; __syncthreads();
    for (int o = 128; o > 0; o >>= 1) {
        if (tid < o) red[tid] += red[tid + o];
        __syncthreads();
    }
    const float mean = red[0] * (1.f / H_);
    __syncthreads();

    float lvar = 0.f;
#pragma unroll
    for (int i = 0; i < 8; i++) { float d = v[i] - mean; lvar += d * d; }
    red[tid] = lvar; __syncthreads();
    for (int o = 128; o > 0; o >>= 1) {
        if (tid < o) red[tid] += red[tid + o];
        __syncthreads();
    }
    const float rstd = rsqrtf(red[0] * (1.f / H_) + EPS_);

#pragma unroll
    for (int i = 0; i < 8; i++) {
        int c = tid + i * 256;
        float nv = (v[i] - mean) * rstd;
        o1[base + c] = __float2half_rn(nv * g1[c] + b1[c]);
        if (o2) o2[base + c] = __float2half_rn(nv * g2[c] + b2[c]);
    }
}

// ---------------------------------------------------------------------------
// Register-resident causal softmax, in place on fp16 buffer.
// ---------------------------------------------------------------------------
__global__ void softmax_f16_kernel(__half* __restrict__ pf) {
    const int q = blockIdx.x;
    const int n = blockIdx.y;
    __half* row = pf + ((size_t)n * S_ + q) * (size_t)S_;
    const int len = q + 1;
    const int tid = threadIdx.x;
    __shared__ float red[256];

    float v[8];
#pragma unroll
    for (int i = 0; i < 8; i++) {
        int idx = tid + i * 256;
        v[i] = (idx < len) ? __half2float(row[idx]) : -3.4e38f;
    }
    float mx = v[0];
#pragma unroll
    for (int i = 1; i < 8; i++) mx = fmaxf(mx, v[i]);
    red[tid] = mx; __syncthreads();
    for (int o = 128; o > 0; o >>= 1) {
        if (tid < o) red[tid] = fmaxf(red[tid], red[tid + o]);
        __syncthreads();
    }
    mx = red[0]; __syncthreads();

    float sum = 0.f;
#pragma unroll
    for (int i = 0; i < 8; i++) {
        int idx = tid + i * 256;
        if (idx < len) { v[i] = expf(v[i] - mx); sum += v[i]; }
    }
    red[tid] = sum; __syncthreads();
    for (int o = 128; o > 0; o >>= 1) {
        if (tid < o) red[tid] += red[tid + o];
        __syncthreads();
    }
    const float inv = 1.f / red[0];

#pragma unroll
    for (int i = 0; i < 8; i++) {
        int idx = tid + i * 256;
        if (idx < len) row[idx] = __float2half_rn(v[i] * inv);
    }
    const int bend = ((q >> 7) + 1) << 7;
    const __half z = __float2half_rn(0.f);
    for (int idx = len + tid; idx < bend; idx += 256) row[idx] = z;
}

// ---------------------------------------------------------------------------
// Single-pass fp16 GEMM: 2-stage cp.async pipeline, BK=64, BN=128 tile,
// MINB CTAs/SM (2 for dense GEMMs: second CTA hides sync/epilogue exposure).
//   EPI: 0 = fp32 store, 1 = gelu -> fp16, 3 = fp16 store,
//        4 = fp16 store with fused bias + NeoX rotary (qkv GEMM).
//   CAUS: skip blocks with n0 > row0+127. CAUSK: K limited to row0+128
//         (block order reversed: longest blocks first).
// ---------------------------------------------------------------------------
template <int EPI, int MINB, bool CAUS, bool CAUSK>
__global__ void __launch_bounds__(256, MINB) gemm_hf(
    const __half* __restrict__ A, int lda, long long sA,
    const __half* __restrict__ B, int ldb, long long sB,
    const float* __restrict__ bias,
    float* __restrict__ C, __half* __restrict__ H16,
    int ldc, long long sC,
    int K, float alpha) {

    constexpr int MI  = 2;                  // BN=128: warps 4m x 2n, 32x64 each
    constexpr int BUF = 16384 + 128 * 128;  // 32 KB per stage

    extern __shared__ char smem[];
    const uint32_t sb = smem_u32(smem);
    const int tid  = threadIdx.x;
    const int lane = tid & 31;
    const int wid  = tid >> 5;
    const int wm   = wid & 3;
    const int wn   = wid >> 2;
    const int mblk = CAUSK ? (gridDim.x - 1 - blockIdx.x) : blockIdx.x;
    const int row0 = mblk * 128;
    const int n0   = blockIdx.y * 128;

    if (CAUS && n0 > row0 + 127) return;

    A += (size_t)blockIdx.z * sA;
    B += (size_t)blockIdx.z * sB;
    if (C)   C   += (size_t)blockIdx.z * sC;
    if (H16) H16 += (size_t)blockIdx.z * sC;

    float acc[MI][8][4];
#pragma unroll
    for (int i = 0; i < MI; i++)
#pragma unroll
        for (int j = 0; j < 8; j++)
#pragma unroll
            for (int e = 0; e < 4; e++) acc[i][j][e] = 0.f;

    const int nch = CAUSK ? ((row0 + 128) >> 6) : (K >> 6);

    for (int c = 0; c <= nch; c++) {
        if (c < nch) {
            const uint32_t bufo = (uint32_t)(c & 1) * BUF;
            const int k0 = c << 6;
#pragma unroll
            for (int i = 0; i < 4; i++) {
                int idx = tid + i * 256;
                int r  = idx >> 3;
                int cc = (idx & 7) * 8;
                uint32_t soff = swz((uint32_t)(r * 128 + cc * 2));
                cpa16(sb + bufo + soff, A + (size_t)(row0 + r) * lda + k0 + cc);
            }
#pragma unroll
            for (int i = 0; i < 4; i++) {
                int idx = tid + i * 256;
                int r  = idx >> 3;
                int cc = (idx & 7) * 8;
                uint32_t soff = swz((uint32_t)(r * 128 + cc * 2));
                cpa16(sb + bufo + 16384 + soff, B + (size_t)(n0 + r) * ldb + k0 + cc);
            }
            asm volatile("cp.async.commit_group;" ::: "memory");
        }
        if (c >= 1) {
            if (c < nch) asm volatile("cp.async.wait_group 1;" ::: "memory");
            else         asm volatile("cp.async.wait_group 0;" ::: "memory");
            __syncthreads();

            const uint32_t bufo = (uint32_t)((c - 1) & 1) * BUF;
            const uint32_t sA16 = sb + bufo;
            const uint32_t sB16 = sA16 + 16384;

#pragma unroll
            for (int ks = 0; ks < 4; ks++) {
                const int kk = ks * 16;
                uint32_t ah[MI][4];
                {
                    const uint32_t arow = (uint32_t)(wm * 32 + (lane & 15));
                    const uint32_t acol = (uint32_t)(kk + (lane >> 4) * 8);
#pragma unroll
                    for (int mi = 0; mi < MI; mi++) {
                        uint32_t off = swz((arow + mi * 16) * 128 + acol * 2);
                        ldsm4(ah[mi], sA16 + off);
                    }
                }
                const uint32_t brow = (uint32_t)(wn * 64 + ((lane >> 4) & 1) * 8 + (lane & 7));
                const uint32_t bcol = (uint32_t)(kk + ((lane >> 3) & 1) * 8);
#pragma unroll
                for (int ng = 0; ng < 4; ng++) {
                    uint32_t bh[4];
                    uint32_t off = swz((brow + ng * 16) * 128 + bcol * 2);
                    ldsm4(bh, sB16 + off);
#pragma unroll
                    for (int mi = 0; mi < MI; mi++) {
#pragma unroll
                        for (int half = 0; half < 2; half++) {
                            mma16816h(acc[mi][ng * 2 + half], ah[mi], bh + half * 2);
                        }
                    }
                }
            }
            __syncthreads();
        }
    }

    const int g = lane >> 2;
    const int t = lane & 3;

    if (EPI == 4) {
        // fold bias into acc (alpha == 1 for qkv)
#pragma unroll
        for (int mi = 0; mi < MI; mi++)
#pragma unroll
            for (int nt = 0; nt < 8; nt++) {
                const int col = n0 + wn * 64 + nt * 8 + 2 * t;
                float2 bv = *(const float2*)(bias + col);
                acc[mi][nt][0] += bv.x; acc[mi][nt][1] += bv.y;
                acc[mi][nt][2] += bv.x; acc[mi][nt][3] += bv.y;
            }
        // NeoX rotary: rot regions [0,32) (q) / [128,160) (k) per 384-col head;
        // warp span starts are 64-aligned; pair (i, i+16) = (nt, nt+2).
        const int m384 = (n0 + wn * 64) % 384;
        if (m384 == 0 || m384 == 128) {
#pragma unroll
            for (int mi = 0; mi < MI; mi++)
#pragma unroll
                for (int nt = 0; nt < 2; nt++)
#pragma unroll
                    for (int e = 0; e < 4; e++) {
                        int i = nt * 8 + 2 * t + (e & 1);
                        int srow = row0 + wm * 32 + mi * 16 + g + ((e >> 1) * 8);
                        float f = expf(-(float)i * 0.575646273248511f);
                        float sn, cs;
                        sincosf((float)srow * f, &sn, &cs);
                        float a  = acc[mi][nt][e];
                        float c2 = acc[mi][nt + 2][e];
                        acc[mi][nt][e]     = a * cs - c2 * sn;
                        acc[mi][nt + 2][e] = c2 * cs + a * sn;
                    }
        }
    }

#pragma unroll
    for (int mi = 0; mi < MI; mi++) {
        const int r = row0 + wm * 32 + mi * 16 + g;
#pragma unroll
        for (int nt = 0; nt < 8; nt++) {
            const int col = n0 + wn * 64 + nt * 8 + 2 * t;
            float2 v0 = make_float2(acc[mi][nt][0] * alpha, acc[mi][nt][1] * alpha);
            float2 v1 = make_float2(acc[mi][nt][2] * alpha, acc[mi][nt][3] * alpha);
            if (EPI != 4 && bias) {
                float2 bv = *(const float2*)(bias + col);
                v0.x += bv.x; v0.y += bv.y;
                v1.x += bv.x; v1.y += bv.y;
            }
            if (EPI == 1 || EPI == 3 || EPI == 4) {
                if (EPI == 1) {
                    v0.x = gelu_f(v0.x); v0.y = gelu_f(v0.y);
                    v1.x = gelu_f(v1.x); v1.y = gelu_f(v1.y);
                }
                *(__half2*)(H16 + (size_t)r * ldc + col)       = __floats2half2_rn(v0.x, v0.y);
                *(__half2*)(H16 + (size_t)(r + 8) * ldc + col) = __floats2half2_rn(v1.x, v1.y);
            } else {
                *(float2*)(C + (size_t)r * ldc + col)       = v0;
                *(float2*)(C + (size_t)(r + 8) * ldc + col) = v1;
            }
        }
    }
}

// ---------------------------------------------------------------------------
// Embedding gather
// ---------------------------------------------------------------------------
__global__ void embed_kernel(const int* __restrict__ x,
                             const float* __restrict__ embed,
                             float* __restrict__ h) {
    int s = blockIdx.y;
    int c = blockIdx.x * 256 + threadIdx.x;
    h[(size_t)s * H_ + c] = embed[(size_t)x[s] * H_ + c];
}

// ---------------------------------------------------------------------------
// Launcher with 3-stream fork/join (capture-safe: full join before return)
// ---------------------------------------------------------------------------
#define SM_B128 (2 * (16384 + 128 * 128))   // 64 KB -> 2 CTAs/SM

extern "C" void kernel_launch(void* const* d_in, const int* in_sizes, int n_in,
                              void* d_out, int out_size) {
    const int*   x        = (const int*)  d_in[0];
    const float* embed    = (const float*)d_in[1];
    const float* ln1_g    = (const float*)d_in[2];
    const float* ln1_b    = (const float*)d_in[3];
    const float* ln2_g    = (const float*)d_in[4];
    const float* ln2_b    = (const float*)d_in[5];
    const float* qkv_w    = (const float*)d_in[6];
    const float* qkv_b    = (const float*)d_in[7];
    const float* dense_w  = (const float*)d_in[8];
    const float* dense_b  = (const float*)d_in[9];
    const float* fc1_w    = (const float*)d_in[10];
    const float* fc1_b    = (const float*)d_in[11];
    const float* fc2_w    = (const float*)d_in[12];
    const float* fc2_b    = (const float*)d_in[13];
    const float* fln_g    = (const float*)d_in[14];
    const float* fln_b    = (const float*)d_in[15];
    const float* logits_w = (const float*)d_in[16];
    float* out = (float*)d_out;

    float *h, *mlp, *attn;
    __half *a1f, *a2f, *ff, *qf, *vtf, *pf, *ctxf, *af;
    __half *wq, *wd, *wf1, *wf2, *wlf;
    cudaGetSymbolAddress((void**)&h,      g_h);
    cudaGetSymbolAddress((void**)&mlp,    g_mlp);
    cudaGetSymbolAddress((void**)&attn,   g_attn);
    cudaGetSymbolAddress((void**)&a1f,    g_a1f);
    cudaGetSymbolAddress((void**)&a2f,    g_a2f);
    cudaGetSymbolAddress((void**)&ff,     g_ff);
    cudaGetSymbolAddress((void**)&qf,     g_qf);
    cudaGetSymbolAddress((void**)&vtf,    g_vtf);
    cudaGetSymbolAddress((void**)&pf,     g_pf);
    cudaGetSymbolAddress((void**)&ctxf,   g_ctxf);
    cudaGetSymbolAddress((void**)&af,     g_af);
    cudaGetSymbolAddress((void**)&wq,     g_wq);
    cudaGetSymbolAddress((void**)&wd,     g_wd);
    cudaGetSymbolAddress((void**)&wf1,    g_wf1);
    cudaGetSymbolAddress((void**)&wf2,    g_wf2);
    cudaGetSymbolAddress((void**)&wlf,    g_wlf);

    cudaFuncSetAttribute((const void*)gemm_hf<0, 2, false, false>,
                         cudaFuncAttributeMaxDynamicSharedMemorySize, SM_B128);
    cudaFuncSetAttribute((const void*)gemm_hf<1, 2, false, false>,
                         cudaFuncAttributeMaxDynamicSharedMemorySize, SM_B128);
    cudaFuncSetAttribute((const void*)gemm_hf<4, 2, false, false>,
                         cudaFuncAttributeMaxDynamicSharedMemorySize, SM_B128);
    cudaFuncSetAttribute((const void*)gemm_hf<3, 2, true, false>,
                         cudaFuncAttributeMaxDynamicSharedMemorySize, SM_B128);
    cudaFuncSetAttribute((const void*)gemm_hf<3, 2, false, true>,
                         cudaFuncAttributeMaxDynamicSharedMemorySize, SM_B128);

    // streams/events created once (first call is the non-captured correctness run)
    static cudaStream_t sW = 0, sM = 0;
    static cudaEvent_t evFork, evW[5], evLn[L_], evMlp[L_], evQkv[L_], evVt[L_];
    if (!sW) {
        cudaStreamCreateWithFlags(&sW, cudaStreamNonBlocking);
        cudaStreamCreateWithFlags(&sM, cudaStreamNonBlocking);
        cudaEventCreateWithFlags(&evFork, cudaEventDisableTiming);
        for (int i = 0; i < 5; i++) cudaEventCreateWithFlags(&evW[i], cudaEventDisableTiming);
        for (int i = 0; i < L_; i++) {
            cudaEventCreateWithFlags(&evLn[i], cudaEventDisableTiming);
            cudaEventCreateWithFlags(&evMlp[i], cudaEventDisableTiming);
            cudaEventCreateWithFlags(&evQkv[i], cudaEventDisableTiming);
            cudaEventCreateWithFlags(&evVt[i], cudaEventDisableTiming);
        }
    }

    const float inv_sqrt_hd = 0.08838834764831845f;  // 1/sqrt(128)

    // ---- fork ----
    cudaEventRecord(evFork, 0);
    cudaStreamWaitEvent(sW, evFork, 0);
    cudaStreamWaitEvent(sM, evFork, 0);

    // ---- weight prep on sW (fp16, z batches both layers) ----
    wsplitf_kernel<<<dim3(H_ / 32, 3 * H_ / 32, L_), 256, 0, sW>>>(
        qkv_w, 3 * H_, H_, 3 * H_, (long long)H_ * 3 * H_, (long long)H_ * 3 * H_, wq);
    cudaEventRecord(evW[0], sW);
    wsplitf_kernel<<<dim3(H_ / 32, FF_ / 32, L_), 256, 0, sW>>>(
        fc1_w, FF_, H_, FF_, (long long)H_ * FF_, (long long)H_ * FF_, wf1);
    cudaEventRecord(evW[1], sW);
    wsplitf_kernel<<<dim3(FF_ / 32, H_ / 32, L_), 256, 0, sW>>>(
        fc2_w, H_, FF_, H_, (long long)FF_ * H_, (long long)FF_ * H_, wf2);
    cudaEventRecord(evW[2], sW);
    wsplitf_kernel<<<dim3(H_ / 32, H_ / 32, L_), 256, 0, sW>>>(
        dense_w, H_, H_, H_, (long long)H_ * H_, (long long)H_ * H_, wd);
    cudaEventRecord(evW[3], sW);
    wsplitf_kernel<<<dim3(H_ / 32, V_ / 32, 1), 256, 0, sW>>>(
        logits_w, V_, H_, V_, 0, 0, wlf);
    cudaEventRecord(evW[4], sW);

    // ---- main path ----
    embed_kernel<<<dim3(H_ / 256, S_), 256>>>(x, embed, h);
    addln_kernel<<<S_, 256>>>(h, nullptr, nullptr,
                              ln1_g, ln1_b, a1f, ln2_g, ln2_b, a2f);
    cudaEventRecord(evLn[0], 0);

    for (int l = 0; l < L_; l++) {
        // ---- MLP branch on sM ----
        cudaStreamWaitEvent(sM, evLn[l], 0);
        cudaStreamWaitEvent(sM, evW[1], 0);
        gemm_hf<1, 2, false, false><<<dim3(S_ / 128, FF_ / 128, 1), 256, SM_B128, sM>>>(
            a2f, H_, 0, wf1 + (size_t)l * H_ * FF_, H_, 0,
            fc1_b + (size_t)l * FF_, nullptr, ff, FF_, 0, H_, 1.f);
        cudaStreamWaitEvent(sM, evW[2], 0);
        gemm_hf<0, 2, false, false><<<dim3(S_ / 128, H_ / 128, 1), 256, SM_B128, sM>>>(
            ff, FF_, 0, wf2 + (size_t)l * FF_ * H_, FF_, 0,
            fc2_b + (size_t)l * H_, mlp, nullptr, H_, 0, FF_, 1.f);
        cudaEventRecord(evMlp[l], sM);

        // ---- attention branch on main ----
        cudaStreamWaitEvent(0, evW[0], 0);
        // qkv GEMM with fused bias + rotary epilogue
        gemm_hf<4, 2, false, false><<<dim3(S_ / 128, 3 * H_ / 128, 1), 256, SM_B128>>>(
            a1f, H_, 0, wq + (size_t)l * H_ * 3 * H_, H_, 0,
            qkv_b + (size_t)l * 3 * H_, nullptr, qf, 3 * H_, 0, H_, 1.f);
        cudaEventRecord(evQkv[l], 0);

        // v transpose on sW (idle after weight prep) in parallel with scores
        cudaStreamWaitEvent(sW, evQkv[l], 0);
        vtranf_kernel<<<dim3(S_ / 32, HD_ / 32, NH_), 256, 0, sW>>>(
            qf + 2 * HD_, 3 * H_, S_, HD_, 3 * HD_, (long long)HD_ * S_, vtf);
        cudaEventRecord(evVt[l], sW);

        // scores = q @ k^T * 1/sqrt(HD)  (fp16 out, causal block-skip) -> pf
        gemm_hf<3, 2, true, false><<<dim3(S_ / 128, S_ / 128, NH_), 256, SM_B128>>>(
            qf, 3 * H_, 3 * HD_,
            qf + HD_, 3 * H_, 3 * HD_,
            nullptr, nullptr, pf, S_, (long long)S_ * S_,
            HD_, inv_sqrt_hd);

        softmax_f16_kernel<<<dim3(S_, NH_), 256>>>(pf);

        // ctx = probs @ v  (fp16, causal K-limit, longest blocks first) -> ctxf
        cudaStreamWaitEvent(0, evVt[l], 0);
        gemm_hf<3, 2, false, true><<<dim3(S_ / 128, 1, NH_), 256, SM_B128>>>(
            pf, S_, (long long)S_ * S_,
            vtf, S_, (long long)HD_ * S_,
            nullptr, nullptr, ctxf, H_, HD_,
            S_, 1.f);

        // attn = ctx @ dense_w + dense_b  (fp32 out)
        cudaStreamWaitEvent(0, evW[3], 0);
        gemm_hf<0, 2, false, false><<<dim3(S_ / 128, H_ / 128, 1), 256, SM_B128>>>(
            ctxf, H_, 0, wd + (size_t)l * H_ * H_, H_, 0,
            dense_b + (size_t)l * H_, attn, nullptr, H_, 0, H_, 1.f);

        // join MLP; fused h += attn + mlp, then LN(s)
        cudaStreamWaitEvent(0, evMlp[l], 0);
        if (l < L_ - 1) {
            addln_kernel<<<S_, 256>>>(h, attn, mlp,
                                      ln1_g + (size_t)(l + 1) * H_,
                                      ln1_b + (size_t)(l + 1) * H_, a1f,
                                      ln2_g + (size_t)(l + 1) * H_,
                                      ln2_b + (size_t)(l + 1) * H_, a2f);
            cudaEventRecord(evLn[l + 1], 0);
        } else {
            addln_kernel<<<S_, 256>>>(h, attn, mlp,
                                      fln_g, fln_b, af,
                                      nullptr, nullptr, nullptr);
        }
    }

    // logits GEMM (joins sW via evW[4])
    cudaStreamWaitEvent(0, evW[4], 0);
    gemm_hf<0, 2, false, false><<<dim3(S_ / 128, V_ / 128, 1), 256, SM_B128>>>(
        af, H_, 0, wlf, H_, 0, nullptr, out, nullptr, V_, 0, H_, 1.f);
}